// round 11
// baseline (speedup 1.0000x reference)
#include <cuda_runtime.h>
#include <cuda_bf16.h>

#define VOCAB 87429
#define EDIM  51
#define NPAIR 32          // bf16 pairs per row (64 cols, 51 real)
#define ERS   36          // emb row stride in SMEM u32 (bank: 36 mod 32 = 4)
#define CCH   39
#define HTOK  8192
#define NJP   40          // padded j count (38 real)
#define TH    256         // h-tile per block in k1
#define NBH   (HTOK / TH) // 32
#define NCZ   13          // channel chunks of 3 (39 = 13*3)
#define SLC   (HTOK * NJP)
#define WELT  (NPAIR * NJP)   // 1280 u32 per channel per weight table

#define SEB   (TH * ERS)                        // 9216 u32 per emb table
#define K1_SMEM_U32 (2 * SEB + 4 * WELT)        // 23552
#define K1_SMEM_BYTES (K1_SMEM_U32 * 4)         // 94208 -> 2 blocks/SM

// scratch (device globals — no allocation allowed)
__device__ unsigned     g_eb [VOCAB * NPAIR];     // emb big  bf16x2 pairs ~11.2 MB
__device__ unsigned     g_es [VOCAB * NPAIR];     // emb small bf16x2 pairs
__device__ unsigned     g_wbp[CCH * WELT];        // weights big  [c][p][j]
__device__ unsigned     g_wsp[CCH * WELT];        // weights small [c][p][j]
__device__ float        g_A   [NCZ * SLC];        // partials, layout [z][j][h]
__device__ float        g_Asum[SLC];              // reduced projections [j][h]
__device__ unsigned int g_max5[5];

// ---------------------------------------------------------------------------
// helpers
// ---------------------------------------------------------------------------
__device__ __forceinline__ unsigned pack2(float lo, float hi) {
    unsigned ulo = (unsigned)__bfloat16_as_ushort(__float2bfloat16_rn(lo));
    unsigned uhi = (unsigned)__bfloat16_as_ushort(__float2bfloat16_rn(hi));
    return (uhi << 16) | ulo;
}
__device__ __forceinline__ float bf_big(float v) {
    return __bfloat162float(__float2bfloat16_rn(v));
}
__device__ __forceinline__ void mma_bf16(float* c, unsigned a0, unsigned a1,
                                         unsigned a2, unsigned a3,
                                         unsigned b0, unsigned b1) {
    asm volatile(
        "mma.sync.aligned.m16n8k16.row.col.f32.bf16.bf16.f32 "
        "{%0,%1,%2,%3}, {%4,%5,%6,%7}, {%8,%9}, {%0,%1,%2,%3};"
        : "+f"(c[0]), "+f"(c[1]), "+f"(c[2]), "+f"(c[3])
        : "r"(a0), "r"(a1), "r"(a2), "r"(a3), "r"(b0), "r"(b1));
}
__device__ __forceinline__ void cpa16(void* dst_smem, const void* src_gmem) {
    unsigned dst = (unsigned)__cvta_generic_to_shared(dst_smem);
    asm volatile("cp.async.ca.shared.global [%0], [%1], 16;\n" :: "r"(dst), "l"(src_gmem));
}
__device__ __forceinline__ void cpa_commit() { asm volatile("cp.async.commit_group;\n"); }
__device__ __forceinline__ void cpa_wait1()  { asm volatile("cp.async.wait_group 1;\n"); }
__device__ __forceinline__ void cpa_wait0()  { asm volatile("cp.async.wait_group 0;\n"); }

// ---------------------------------------------------------------------------
// kernel -1: zero the 5 branch maxima (keeps k1 at ncu's profiled slot)
// ---------------------------------------------------------------------------
__global__ void kzero() {
    if (threadIdx.x < 5) g_max5[threadIdx.x] = 0u;
}

// ---------------------------------------------------------------------------
// kernel 0a: split embedding into bf16x2 big/small pair tables
//   pair p of row r = (e=2p, e=2p+1), zeros beyond EDIM
// ---------------------------------------------------------------------------
__global__ void kpad_emb(const float* __restrict__ emb) {
    int idx = blockIdx.x * blockDim.x + threadIdx.x;
    if (idx >= VOCAB * NPAIR) return;
    int r = idx >> 5;
    int p = idx & 31;
    int e0 = 2 * p, e1 = 2 * p + 1;
    float v0 = (e0 < EDIM) ? emb[r * EDIM + e0] : 0.0f;
    float v1 = (e1 < EDIM) ? emb[r * EDIM + e1] : 0.0f;
    float b0 = bf_big(v0), b1 = bf_big(v1);
    g_eb[idx] = pack2(b0, b1);
    g_es[idx] = pack2(v0 - b0, v1 - b1);
}

// ---------------------------------------------------------------------------
// kernel 0b: pack conv weights into bf16x2 pair tables [c][p][j]
//   j: br0 -> 0; br1 -> 1..2; br2 -> 3..7; br3 -> 8..17; br4 -> 18..37
// ---------------------------------------------------------------------------
__device__ __forceinline__ float wfetch(const float* w0, const float* w1,
                                        const float* w2, const float* w3,
                                        const float* w4, int c, int j, int e) {
    if (j >= 38 || e >= EDIM) return 0.0f;
    const float* wp; int kk, dk;
    if      (j < 1)  { wp = w0; kk = 1;  dk = j; }
    else if (j < 3)  { wp = w1; kk = 2;  dk = j - 1; }
    else if (j < 8)  { wp = w2; kk = 5;  dk = j - 3; }
    else if (j < 18) { wp = w3; kk = 10; dk = j - 8; }
    else             { wp = w4; kk = 20; dk = j - 18; }
    return wp[(c * kk + dk) * EDIM + e];
}

__global__ void kpack_w(const float* __restrict__ w0, const float* __restrict__ w1,
                        const float* __restrict__ w2, const float* __restrict__ w3,
                        const float* __restrict__ w4) {
    int idx = blockIdx.x * blockDim.x + threadIdx.x;
    if (idx >= CCH * WELT) return;
    int c   = idx / WELT;
    int rem = idx - c * WELT;
    int p   = rem / NJP;
    int j   = rem - p * NJP;
    float v0 = wfetch(w0, w1, w2, w3, w4, c, j, 2 * p);
    float v1 = wfetch(w0, w1, w2, w3, w4, c, j, 2 * p + 1);
    float b0 = bf_big(v0), b1 = bf_big(v1);
    g_wbp[idx] = pack2(b0, b1);
    g_wsp[idx] = pack2(v0 - b0, v1 - b1);
}

// ---------------------------------------------------------------------------
// kernel 1: A_z[j][h] = sum_{c in chunk z} emb[tok[c,h]] . W[c][j]
//   bf16 m16n8k16 mma, 3-term bf16 split (bB + bS + sB), operands PRE-SPLIT
//   so the hot loop is pure LDS.32 -> mma (no cvt/lop3/fsub).
//   128 threads = 4 warps; each warp 64 h x 40 j (4 m16 x 5 n8), 20 acc tiles.
//   94 KB smem -> 2 blocks/SM. Weights double-buffered, emb single-buffered.
// ---------------------------------------------------------------------------
__global__ __launch_bounds__(128, 2) void k1_dots(const int* __restrict__ tokens) {
    extern __shared__ unsigned smu[];
    unsigned* s_eb  = smu;                        // [TH][ERS]
    unsigned* s_es  = smu + SEB;                  // [TH][ERS]
    unsigned* s_wbp = smu + 2 * SEB;              // [2][WELT]
    unsigned* s_wsp = smu + 2 * SEB + 2 * WELT;   // [2][WELT]

    const int tid  = threadIdx.x;
    const int h0   = blockIdx.x * TH;
    const int z    = blockIdx.y;
    const int cbeg = z * 3;                       // always 3 channels

    const int w    = tid >> 5;        // warp 0..3
    const int lane = tid & 31;
    const int g    = lane >> 2;       // 0..7
    const int t    = lane & 3;        // 0..3

    // staging: each thread handles emb rows tid and tid+128
    int tkA[3], tkB[3];
    #pragma unroll
    for (int i = 0; i < 3; i++) {
        tkA[i] = tokens[(cbeg + i) * HTOK + h0 + tid];
        tkB[i] = tokens[(cbeg + i) * HTOK + h0 + tid + 128];
    }

    #define STAGE_W(CC, B) do {                                               \
        const float4* sb = (const float4*)&g_wbp[(cbeg + (CC)) * WELT];       \
        const float4* ss = (const float4*)&g_wsp[(cbeg + (CC)) * WELT];       \
        unsigned* db = &s_wbp[(B) * WELT];                                    \
        unsigned* ds = &s_wsp[(B) * WELT];                                    \
        _Pragma("unroll")                                                     \
        for (int q = 0; q < 3; q++) {                                         \
            int idx = tid + q * 128;                                          \
            if (idx < WELT / 4) {                                             \
                cpa16(db + idx * 4, sb + idx);                                \
                cpa16(ds + idx * 4, ss + idx);                                \
            }                                                                 \
        }                                                                     \
    } while (0)

    #define STAGE_E(CC) do {                                                  \
        const float4* sbA = (const float4*)&g_eb[tkA[(CC)] * NPAIR];          \
        const float4* ssA = (const float4*)&g_es[tkA[(CC)] * NPAIR];          \
        const float4* sbB = (const float4*)&g_eb[tkB[(CC)] * NPAIR];          \
        const float4* ssB = (const float4*)&g_es[tkB[(CC)] * NPAIR];          \
        unsigned* dbA = &s_eb[tid * ERS];                                     \
        unsigned* dsA = &s_es[tid * ERS];                                     \
        unsigned* dbB = &s_eb[(tid + 128) * ERS];                             \
        unsigned* dsB = &s_es[(tid + 128) * ERS];                             \
        _Pragma("unroll")                                                     \
        for (int q = 0; q < 8; q++) {                                         \
            cpa16(dbA + q * 4, sbA + q);                                      \
            cpa16(dsA + q * 4, ssA + q);                                      \
            cpa16(dbB + q * 4, sbB + q);                                      \
            cpa16(dsB + q * 4, ssB + q);                                      \
        }                                                                     \
    } while (0)

    float acc[4][5][4];
    #pragma unroll
    for (int mt = 0; mt < 4; mt++)
        #pragma unroll
        for (int nb = 0; nb < 5; nb++)
            #pragma unroll
            for (int r = 0; r < 4; r++) acc[mt][nb][r] = 0.0f;

    #define COMPUTE(BW) do {                                                  \
        const unsigned* eb = &s_eb[w * 64 * ERS];                             \
        const unsigned* es = &s_es[w * 64 * ERS];                             \
        const unsigned* wbp = &s_wbp[(BW) * WELT];                            \
        const unsigned* wsp = &s_wsp[(BW) * WELT];                            \
        _Pragma("unroll")                                                     \
        for (int ks = 0; ks < 4; ks++) {                                      \
            const int p0 = ks * 8;                                            \
            unsigned aB[4][4], aS[4][4];                                      \
            _Pragma("unroll")                                                 \
            for (int mt = 0; mt < 4; mt++) {                                  \
                const unsigned* rb = eb + (mt * 16 + g) * ERS + p0 + t;       \
                const unsigned* rs = es + (mt * 16 + g) * ERS + p0 + t;       \
                aB[mt][0] = rb[0];                                            \
                aB[mt][1] = rb[8 * ERS];                                      \
                aB[mt][2] = rb[4];                                            \
                aB[mt][3] = rb[8 * ERS + 4];                                  \
                aS[mt][0] = rs[0];                                            \
                aS[mt][1] = rs[8 * ERS];                                      \
                aS[mt][2] = rs[4];                                            \
                aS[mt][3] = rs[8 * ERS + 4];                                  \
            }                                                                 \
            _Pragma("unroll")                                                 \
            for (int nb = 0; nb < 5; nb++) {                                  \
                const int jo = nb * 8 + g;                                    \
                unsigned b0b = wbp[(p0 + t) * NJP + jo];                      \
                unsigned b1b = wbp[(p0 + t + 4) * NJP + jo];                  \
                unsigned b0s = wsp[(p0 + t) * NJP + jo];                      \
                unsigned b1s = wsp[(p0 + t + 4) * NJP + jo];                  \
                _Pragma("unroll")                                             \
                for (int mt = 0; mt < 4; mt++) {                              \
                    mma_bf16(acc[mt][nb], aB[mt][0], aB[mt][1], aB[mt][2],    \
                             aB[mt][3], b0b, b1b);                            \
                    mma_bf16(acc[mt][nb], aB[mt][0], aB[mt][1], aB[mt][2],    \
                             aB[mt][3], b0s, b1s);                            \
                    mma_bf16(acc[mt][nb], aS[mt][0], aS[mt][1], aS[mt][2],    \
                             aS[mt][3], b0b, b1b);                            \
                }                                                             \
            }                                                                 \
        }                                                                     \
    } while (0)

    // pipeline: weights one-ahead (double buffer), emb single buffer
    STAGE_W(0, 0); STAGE_E(0); cpa_commit();   // G0 = {w0, emb0}
    STAGE_W(1, 1); cpa_commit();               // G1 = {w1}

    cpa_wait1();                 // G0 done
    __syncthreads();
    COMPUTE(0);                  // channel 0
    __syncthreads();
    STAGE_E(1); cpa_commit();    // G2 = {emb1}
    STAGE_W(2, 0); cpa_commit(); // G3 = {w2}

    cpa_wait1();                 // G1, G2 done
    __syncthreads();
    COMPUTE(1);                  // channel 1
    __syncthreads();
    STAGE_E(2); cpa_commit();    // G4 = {emb2}

    cpa_wait0();                 // G3, G4 done
    __syncthreads();
    COMPUTE(0);                  // channel 2

    #undef STAGE_W
    #undef STAGE_E
    #undef COMPUTE

    // epilogue: write transposed A[z][j][h]
    float* Az = &g_A[z * SLC];
    #pragma unroll
    for (int mt = 0; mt < 4; mt++) {
        const int h = h0 + w * 64 + mt * 16 + g;
        #pragma unroll
        for (int nb = 0; nb < 5; nb++) {
            const int j0 = nb * 8 + 2 * t;
            Az[j0 * HTOK + h]           = acc[mt][nb][0];
            Az[(j0 + 1) * HTOK + h]     = acc[mt][nb][1];
            Az[j0 * HTOK + h + 8]       = acc[mt][nb][2];
            Az[(j0 + 1) * HTOK + h + 8] = acc[mt][nb][3];
        }
    }
}

// ---------------------------------------------------------------------------
// kernel 1b: reduce the 13 partial slices -> A_sum[j][h] (L2-hot)
// ---------------------------------------------------------------------------
__global__ void k1_reduce() {
    int idx = blockIdx.x * 256 + threadIdx.x;
    if (idx >= SLC) return;
    float s = 0.0f;
    #pragma unroll
    for (int z = 0; z < NCZ; z++) s += g_A[z * SLC + idx];
    g_Asum[idx] = s;
}

// ---------------------------------------------------------------------------
// kernel 2: per-(h-block, branch) max of relu(conv+b) on A_sum[j][h]
// ---------------------------------------------------------------------------
__global__ void k2_branch(const float* __restrict__ b0, const float* __restrict__ b1,
                          const float* __restrict__ b2, const float* __restrict__ b3,
                          const float* __restrict__ b4) {
    __shared__ unsigned int sm;
    const int tid = threadIdx.x;       // 256
    const int br  = blockIdx.y;
    const int h   = blockIdx.x * 256 + tid;
    if (tid == 0) sm = 0u;
    __syncthreads();

    const int base[5] = {0, 1, 3, 8, 18};
    const int cnt [5] = {1, 2, 5, 10, 20};
    const int k = cnt[br];

    float val = 0.0f;
    if (h <= HTOK - k) {
        float y = 0.0f;
        const float* Ap = g_Asum + base[br] * HTOK + h;
        #pragma unroll 5
        for (int d = 0; d < k; d++)
            y += Ap[d * (HTOK + 1)];
        const float* bp = (br == 0) ? b0 : (br == 1) ? b1 : (br == 2) ? b2
                        : (br == 3) ? b3 : b4;
        val = fmaxf(y + *bp, 0.0f);
    }
    #pragma unroll
    for (int off = 16; off; off >>= 1)
        val = fmaxf(val, __shfl_xor_sync(0xffffffffu, val, off));
    if ((tid & 31) == 0) atomicMax(&sm, __float_as_uint(val));
    __syncthreads();
    if (tid == 0) atomicMax(&g_max5[br], sm);
}

// ---------------------------------------------------------------------------
// kernel 3: 5 -> 8 linear, relu, softmax -> out[8]
// ---------------------------------------------------------------------------
__global__ void k3_head(const float* __restrict__ lin_w, const float* __restrict__ lin_b,
                        float* __restrict__ out) {
    if (threadIdx.x != 0 || blockIdx.x != 0) return;
    float f[5];
    #pragma unroll
    for (int i = 0; i < 5; i++) f[i] = __uint_as_float(g_max5[i]);
    float lg[8], mx = -1e30f;
    #pragma unroll
    for (int o = 0; o < 8; o++) {
        float s = lin_b[o];
        #pragma unroll
        for (int i = 0; i < 5; i++) s += lin_w[o * 5 + i] * f[i];
        s = fmaxf(s, 0.0f);
        lg[o] = s;
        mx = fmaxf(mx, s);
    }
    float den = 0.0f;
    #pragma unroll
    for (int o = 0; o < 8; o++) { lg[o] = expf(lg[o] - mx); den += lg[o]; }
    #pragma unroll
    for (int o = 0; o < 8; o++) out[o] = lg[o] / den;
}

// ---------------------------------------------------------------------------
extern "C" void kernel_launch(void* const* d_in, const int* in_sizes, int n_in,
                              void* d_out, int out_size) {
    const int*   tokens = (const int*)  d_in[0];
    const float* emb    = (const float*)d_in[1];
    const float* lin_w  = (const float*)d_in[2];
    const float* lin_b  = (const float*)d_in[3];
    const float* w0     = (const float*)d_in[4];
    const float* b0     = (const float*)d_in[5];
    const float* w1     = (const float*)d_in[6];
    const float* b1     = (const float*)d_in[7];
    const float* w2     = (const float*)d_in[8];
    const float* b2     = (const float*)d_in[9];
    const float* w3     = (const float*)d_in[10];
    const float* b3     = (const float*)d_in[11];
    const float* w4     = (const float*)d_in[12];
    const float* b4     = (const float*)d_in[13];
    float* out = (float*)d_out;

    static int smem_set = 0;
    if (!smem_set) {
        cudaFuncSetAttribute(k1_dots, cudaFuncAttributeMaxDynamicSharedMemorySize,
                             K1_SMEM_BYTES);
        smem_set = 1;
    }

    kzero    <<<1, 32>>>();
    kpad_emb <<<(VOCAB * NPAIR + 255) / 256, 256>>>(emb);
    kpack_w  <<<(CCH * WELT + 255) / 256, 256>>>(w0, w1, w2, w3, w4);
    k1_dots  <<<dim3(NBH, NCZ), 128, K1_SMEM_BYTES>>>(tokens);
    k1_reduce<<<(SLC + 255) / 256, 256>>>();
    k2_branch<<<dim3(HTOK / 256, 5), 256>>>(b0, b1, b2, b3, b4);
    k3_head  <<<1, 32>>>(lin_w, lin_b, out);
}

// round 13
// speedup vs baseline: 1.5435x; 1.5435x over previous
#include <cuda_runtime.h>
#include <cuda_bf16.h>

#define VOCAB 87429
#define EDIM  51
#define NPAIR 32          // bf16 pairs per row: 32 u32 = 128 B = exactly 1 line
#define ERS   36          // emb row stride in SMEM u32 (conflict-free frags)
#define CCH   39
#define HTOK  8192
#define NJP   40          // padded j count (38 real)
#define TH    256         // h-tile per block in k1
#define NBH   (HTOK / TH) // 32
#define NCZ   13          // channel chunks of 3 (39 = 13*3)
#define SLC   (HTOK * NJP)
#define WELT  (NPAIR * NJP)   // 1280 u32 per channel per weight table

#define SEB   (TH * ERS)                              // 9216 u32 per emb table
#define K1_SMEM_U32 (3 * TH + 2 * SEB + 4 * WELT)     // 24320
#define K1_SMEM_BYTES (K1_SMEM_U32 * 4)               // 97280 -> 2 blocks/SM

// scratch (device globals — no allocation allowed)
__device__ unsigned     g_eb [VOCAB * NPAIR];     // emb big  bf16x2 pairs ~11.2 MB
__device__ unsigned     g_es [VOCAB * NPAIR];     // emb small bf16x2 pairs
__device__ unsigned     g_wbp[CCH * WELT];        // weights big  [c][p][j]
__device__ unsigned     g_wsp[CCH * WELT];        // weights small [c][p][j]
__device__ float        g_A   [NCZ * SLC];        // partials, layout [z][j][h]
__device__ float        g_Asum[SLC];              // reduced projections [j][h]
__device__ unsigned int g_max5[5];

// ---------------------------------------------------------------------------
// helpers
// ---------------------------------------------------------------------------
__device__ __forceinline__ unsigned pack2(float lo, float hi) {
    unsigned ulo = (unsigned)__bfloat16_as_ushort(__float2bfloat16_rn(lo));
    unsigned uhi = (unsigned)__bfloat16_as_ushort(__float2bfloat16_rn(hi));
    return (uhi << 16) | ulo;
}
__device__ __forceinline__ float bf_big(float v) {
    return __bfloat162float(__float2bfloat16_rn(v));
}
__device__ __forceinline__ void mma_bf16(float* c, unsigned a0, unsigned a1,
                                         unsigned a2, unsigned a3,
                                         unsigned b0, unsigned b1) {
    asm volatile(
        "mma.sync.aligned.m16n8k16.row.col.f32.bf16.bf16.f32 "
        "{%0,%1,%2,%3}, {%4,%5,%6,%7}, {%8,%9}, {%0,%1,%2,%3};"
        : "+f"(c[0]), "+f"(c[1]), "+f"(c[2]), "+f"(c[3])
        : "r"(a0), "r"(a1), "r"(a2), "r"(a3), "r"(b0), "r"(b1));
}
__device__ __forceinline__ void cpa16(void* dst_smem, const void* src_gmem) {
    unsigned dst = (unsigned)__cvta_generic_to_shared(dst_smem);
    asm volatile("cp.async.ca.shared.global [%0], [%1], 16;\n" :: "r"(dst), "l"(src_gmem));
}
__device__ __forceinline__ void cpa_commit() { asm volatile("cp.async.commit_group;\n"); }
__device__ __forceinline__ void cpa_wait1()  { asm volatile("cp.async.wait_group 1;\n"); }
__device__ __forceinline__ void cpa_wait0()  { asm volatile("cp.async.wait_group 0;\n"); }

// ---------------------------------------------------------------------------
// kernel -1: zero the 5 branch maxima (keeps k1 at ncu's profiled slot)
// ---------------------------------------------------------------------------
__global__ void kzero() {
    if (threadIdx.x < 5) g_max5[threadIdx.x] = 0u;
}

// ---------------------------------------------------------------------------
// kernel 0a: split embedding into bf16x2 big/small pair tables
// ---------------------------------------------------------------------------
__global__ void kpad_emb(const float* __restrict__ emb) {
    int idx = blockIdx.x * blockDim.x + threadIdx.x;
    if (idx >= VOCAB * NPAIR) return;
    int r = idx >> 5;
    int p = idx & 31;
    int e0 = 2 * p, e1 = 2 * p + 1;
    float v0 = (e0 < EDIM) ? emb[r * EDIM + e0] : 0.0f;
    float v1 = (e1 < EDIM) ? emb[r * EDIM + e1] : 0.0f;
    float b0 = bf_big(v0), b1 = bf_big(v1);
    g_eb[idx] = pack2(b0, b1);
    g_es[idx] = pack2(v0 - b0, v1 - b1);
}

// ---------------------------------------------------------------------------
// kernel 0b: pack conv weights into bf16x2 pair tables [c][p][j]
// ---------------------------------------------------------------------------
__device__ __forceinline__ float wfetch(const float* w0, const float* w1,
                                        const float* w2, const float* w3,
                                        const float* w4, int c, int j, int e) {
    if (j >= 38 || e >= EDIM) return 0.0f;
    const float* wp; int kk, dk;
    if      (j < 1)  { wp = w0; kk = 1;  dk = j; }
    else if (j < 3)  { wp = w1; kk = 2;  dk = j - 1; }
    else if (j < 8)  { wp = w2; kk = 5;  dk = j - 3; }
    else if (j < 18) { wp = w3; kk = 10; dk = j - 8; }
    else             { wp = w4; kk = 20; dk = j - 18; }
    return wp[(c * kk + dk) * EDIM + e];
}

__global__ void kpack_w(const float* __restrict__ w0, const float* __restrict__ w1,
                        const float* __restrict__ w2, const float* __restrict__ w3,
                        const float* __restrict__ w4) {
    int idx = blockIdx.x * blockDim.x + threadIdx.x;
    if (idx >= CCH * WELT) return;
    int c   = idx / WELT;
    int rem = idx - c * WELT;
    int p   = rem / NJP;
    int j   = rem - p * NJP;
    float v0 = wfetch(w0, w1, w2, w3, w4, c, j, 2 * p);
    float v1 = wfetch(w0, w1, w2, w3, w4, c, j, 2 * p + 1);
    float b0 = bf_big(v0), b1 = bf_big(v1);
    g_wbp[idx] = pack2(b0, b1);
    g_wsp[idx] = pack2(v0 - b0, v1 - b1);
}

// ---------------------------------------------------------------------------
// kernel 1: A_z[j][h] = sum_{c in chunk z} emb[tok[c,h]] . W[c][j]
//   bf16 m16n8k16 mma, 3-term pre-split (bB + bS + sB).
//   COALESCED GATHER: one emb row = one 128B line; 8 lanes stage one row
//   (4 rows / 4 lines / ~4 wavefronts per cp.async instruction, vs 32 before).
//   256 threads = 8 warps, warp = 32h x 40j (mt=2); 97 KB -> 2 blocks/SM.
// ---------------------------------------------------------------------------
__global__ __launch_bounds__(256, 2) void k1_dots(const int* __restrict__ tokens) {
    extern __shared__ unsigned smu[];
    unsigned* s_tok = smu;                              // [3][TH]
    unsigned* s_eb  = smu + 3 * TH;                     // [TH][ERS]
    unsigned* s_es  = s_eb + SEB;                       // [TH][ERS]
    unsigned* s_wbp = s_es + SEB;                       // [2][WELT]
    unsigned* s_wsp = s_wbp + 2 * WELT;                 // [2][WELT]

    const int tid  = threadIdx.x;
    const int h0   = blockIdx.x * TH;
    const int z    = blockIdx.y;
    const int cbeg = z * 3;                             // always 3 channels

    const int w    = tid >> 5;        // warp 0..7
    const int lane = tid & 31;
    const int g    = lane >> 2;       // 0..7
    const int t    = lane & 3;        // 0..3
    const int l8   = lane >> 3;       // 0..3 : row within 4-row group
    const int lo   = lane & 7;        // 0..7 : 16B chunk within row

    // tokens for all 3 channels into smem (coalesced)
    #pragma unroll
    for (int i = 0; i < 3; i++)
        s_tok[i * TH + tid] = (unsigned)tokens[(cbeg + i) * HTOK + h0 + tid];
    __syncthreads();

    #define STAGE_W(CC, B) do {                                               \
        const float4* sb = (const float4*)&g_wbp[(cbeg + (CC)) * WELT];       \
        const float4* ss = (const float4*)&g_wsp[(cbeg + (CC)) * WELT];       \
        unsigned* db = &s_wbp[(B) * WELT];                                    \
        unsigned* ds = &s_wsp[(B) * WELT];                                    \
        _Pragma("unroll")                                                     \
        for (int q = 0; q < 2; q++) {                                         \
            int idx = tid + q * 256;                                          \
            if (idx < WELT / 4) {                                             \
                cpa16(db + idx * 4, sb + idx);                                \
                cpa16(ds + idx * 4, ss + idx);                                \
            }                                                                 \
        }                                                                     \
    } while (0)

    // coalesced: warp stages 4 rows per iteration, 8 iterations = 32 rows,
    // 8 warps cover all 256 rows; big+small per iteration.
    #define STAGE_E(CC) do {                                                  \
        _Pragma("unroll")                                                     \
        for (int it = 0; it < 8; it++) {                                      \
            int row = it * 32 + w * 4 + l8;                                   \
            int tok = (int)s_tok[(CC) * TH + row];                            \
            cpa16(s_eb + row * ERS + lo * 4, g_eb + tok * NPAIR + lo * 4);    \
            cpa16(s_es + row * ERS + lo * 4, g_es + tok * NPAIR + lo * 4);    \
        }                                                                     \
    } while (0)

    float acc[2][5][4];
    #pragma unroll
    for (int mt = 0; mt < 2; mt++)
        #pragma unroll
        for (int nb = 0; nb < 5; nb++)
            #pragma unroll
            for (int r = 0; r < 4; r++) acc[mt][nb][r] = 0.0f;

    #define COMPUTE(BW) do {                                                  \
        const unsigned* eb = &s_eb[w * 32 * ERS];                             \
        const unsigned* es = &s_es[w * 32 * ERS];                             \
        const unsigned* wbp = &s_wbp[(BW) * WELT];                            \
        const unsigned* wsp = &s_wsp[(BW) * WELT];                            \
        _Pragma("unroll")                                                     \
        for (int ks = 0; ks < 4; ks++) {                                      \
            const int p0 = ks * 8;                                            \
            unsigned aB[2][4], aS[2][4];                                      \
            _Pragma("unroll")                                                 \
            for (int mt = 0; mt < 2; mt++) {                                  \
                const unsigned* rb = eb + (mt * 16 + g) * ERS + p0 + t;       \
                const unsigned* rs = es + (mt * 16 + g) * ERS + p0 + t;       \
                aB[mt][0] = rb[0];                                            \
                aB[mt][1] = rb[8 * ERS];                                      \
                aB[mt][2] = rb[4];                                            \
                aB[mt][3] = rb[8 * ERS + 4];                                  \
                aS[mt][0] = rs[0];                                            \
                aS[mt][1] = rs[8 * ERS];                                      \
                aS[mt][2] = rs[4];                                            \
                aS[mt][3] = rs[8 * ERS + 4];                                  \
            }                                                                 \
            _Pragma("unroll")                                                 \
            for (int nb = 0; nb < 5; nb++) {                                  \
                const int jo = nb * 8 + g;                                    \
                unsigned b0b = wbp[(p0 + t) * NJP + jo];                      \
                unsigned b1b = wbp[(p0 + t + 4) * NJP + jo];                  \
                unsigned b0s = wsp[(p0 + t) * NJP + jo];                      \
                unsigned b1s = wsp[(p0 + t + 4) * NJP + jo];                  \
                _Pragma("unroll")                                             \
                for (int mt = 0; mt < 2; mt++) {                              \
                    mma_bf16(acc[mt][nb], aB[mt][0], aB[mt][1], aB[mt][2],    \
                             aB[mt][3], b0b, b1b);                            \
                    mma_bf16(acc[mt][nb], aB[mt][0], aB[mt][1], aB[mt][2],    \
                             aB[mt][3], b0s, b1s);                            \
                    mma_bf16(acc[mt][nb], aS[mt][0], aS[mt][1], aS[mt][2],    \
                             aS[mt][3], b0b, b1b);                            \
                }                                                             \
            }                                                                 \
        }                                                                     \
    } while (0)

    // pipeline: weights one-ahead (double buffer), emb single buffer
    STAGE_W(0, 0); STAGE_E(0); cpa_commit();   // G0 = {w0, emb0}
    STAGE_W(1, 1); cpa_commit();               // G1 = {w1}

    cpa_wait1();                 // G0 done
    __syncthreads();
    COMPUTE(0);                  // channel 0
    __syncthreads();
    STAGE_E(1); cpa_commit();    // G2 = {emb1}
    STAGE_W(2, 0); cpa_commit(); // G3 = {w2}

    cpa_wait1();                 // G1, G2 done
    __syncthreads();
    COMPUTE(1);                  // channel 1
    __syncthreads();
    STAGE_E(2); cpa_commit();    // G4 = {emb2}

    cpa_wait0();                 // G3, G4 done
    __syncthreads();
    COMPUTE(0);                  // channel 2

    #undef STAGE_W
    #undef STAGE_E
    #undef COMPUTE

    // epilogue: write transposed A[z][j][h]
    float* Az = &g_A[z * SLC];
    #pragma unroll
    for (int mt = 0; mt < 2; mt++) {
        const int h = h0 + w * 32 + mt * 16 + g;
        #pragma unroll
        for (int nb = 0; nb < 5; nb++) {
            const int j0 = nb * 8 + 2 * t;
            Az[j0 * HTOK + h]           = acc[mt][nb][0];
            Az[(j0 + 1) * HTOK + h]     = acc[mt][nb][1];
            Az[j0 * HTOK + h + 8]       = acc[mt][nb][2];
            Az[(j0 + 1) * HTOK + h + 8] = acc[mt][nb][3];
        }
    }
}

// ---------------------------------------------------------------------------
// kernel 1b: reduce the 13 partial slices -> A_sum[j][h] (L2-hot)
// ---------------------------------------------------------------------------
__global__ void k1_reduce() {
    int idx = blockIdx.x * 256 + threadIdx.x;
    if (idx >= SLC) return;
    float s = 0.0f;
    #pragma unroll
    for (int z = 0; z < NCZ; z++) s += g_A[z * SLC + idx];
    g_Asum[idx] = s;
}

// ---------------------------------------------------------------------------
// kernel 2: per-(h-block, branch) max of relu(conv+b) on A_sum[j][h]
// ---------------------------------------------------------------------------
__global__ void k2_branch(const float* __restrict__ b0, const float* __restrict__ b1,
                          const float* __restrict__ b2, const float* __restrict__ b3,
                          const float* __restrict__ b4) {
    __shared__ unsigned int sm;
    const int tid = threadIdx.x;       // 256
    const int br  = blockIdx.y;
    const int h   = blockIdx.x * 256 + tid;
    if (tid == 0) sm = 0u;
    __syncthreads();

    const int base[5] = {0, 1, 3, 8, 18};
    const int cnt [5] = {1, 2, 5, 10, 20};
    const int k = cnt[br];

    float val = 0.0f;
    if (h <= HTOK - k) {
        float y = 0.0f;
        const float* Ap = g_Asum + base[br] * HTOK + h;
        #pragma unroll 5
        for (int d = 0; d < k; d++)
            y += Ap[d * (HTOK + 1)];
        const float* bp = (br == 0) ? b0 : (br == 1) ? b1 : (br == 2) ? b2
                        : (br == 3) ? b3 : b4;
        val = fmaxf(y + *bp, 0.0f);
    }
    #pragma unroll
    for (int off = 16; off; off >>= 1)
        val = fmaxf(val, __shfl_xor_sync(0xffffffffu, val, off));
    if ((tid & 31) == 0) atomicMax(&sm, __float_as_uint(val));
    __syncthreads();
    if (tid == 0) atomicMax(&g_max5[br], sm);
}

// ---------------------------------------------------------------------------
// kernel 3: 5 -> 8 linear, relu, softmax -> out[8]
// ---------------------------------------------------------------------------
__global__ void k3_head(const float* __restrict__ lin_w, const float* __restrict__ lin_b,
                        float* __restrict__ out) {
    if (threadIdx.x != 0 || blockIdx.x != 0) return;
    float f[5];
    #pragma unroll
    for (int i = 0; i < 5; i++) f[i] = __uint_as_float(g_max5[i]);
    float lg[8], mx = -1e30f;
    #pragma unroll
    for (int o = 0; o < 8; o++) {
        float s = lin_b[o];
        #pragma unroll
        for (int i = 0; i < 5; i++) s += lin_w[o * 5 + i] * f[i];
        s = fmaxf(s, 0.0f);
        lg[o] = s;
        mx = fmaxf(mx, s);
    }
    float den = 0.0f;
    #pragma unroll
    for (int o = 0; o < 8; o++) { lg[o] = expf(lg[o] - mx); den += lg[o]; }
    #pragma unroll
    for (int o = 0; o < 8; o++) out[o] = lg[o] / den;
}

// ---------------------------------------------------------------------------
extern "C" void kernel_launch(void* const* d_in, const int* in_sizes, int n_in,
                              void* d_out, int out_size) {
    const int*   tokens = (const int*)  d_in[0];
    const float* emb    = (const float*)d_in[1];
    const float* lin_w  = (const float*)d_in[2];
    const float* lin_b  = (const float*)d_in[3];
    const float* w0     = (const float*)d_in[4];
    const float* b0     = (const float*)d_in[5];
    const float* w1     = (const float*)d_in[6];
    const float* b1     = (const float*)d_in[7];
    const float* w2     = (const float*)d_in[8];
    const float* b2     = (const float*)d_in[9];
    const float* w3     = (const float*)d_in[10];
    const float* b3     = (const float*)d_in[11];
    const float* w4     = (const float*)d_in[12];
    const float* b4     = (const float*)d_in[13];
    float* out = (float*)d_out;

    static int smem_set = 0;
    if (!smem_set) {
        cudaFuncSetAttribute(k1_dots, cudaFuncAttributeMaxDynamicSharedMemorySize,
                             K1_SMEM_BYTES);
        smem_set = 1;
    }

    kzero    <<<1, 32>>>();
    kpad_emb <<<(VOCAB * NPAIR + 255) / 256, 256>>>(emb);
    kpack_w  <<<(CCH * WELT + 255) / 256, 256>>>(w0, w1, w2, w3, w4);
    k1_dots  <<<dim3(NBH, NCZ), 256, K1_SMEM_BYTES>>>(tokens);
    k1_reduce<<<(SLC + 255) / 256, 256>>>();
    k2_branch<<<dim3(HTOK / 256, 5), 256>>>(b0, b1, b2, b3, b4);
    k3_head  <<<1, 32>>>(lin_w, lin_b, out);
}